// round 14
// baseline (speedup 1.0000x reference)
#include <cuda_runtime.h>
#include <cuda_bf16.h>
#include <cstdint>
#include <cstring>

__device__ float g_att[32 * 32];
__device__ float g_Sp[8 * 2048];
__device__ float g_cntp[8 * 32];
__device__ float g_rout[2048];
__device__ unsigned g_ctr;
__device__ uint4 g_w1f[32 * 32];   // layer1 B frags, 2 k-steps packed: [(j*2+kp)*32 + lane]
__device__ uint4 g_w2f[32 * 32];   // layer2 B frags, 2 k-steps packed: [(j*4+kp)*32 + lane]

__device__ __forceinline__ float gelu_exact(float x) {
    return 0.5f * x * (1.0f + erff(x * 0.7071067811865476f));
}
__device__ __forceinline__ float ex2_approx(float x) {
    float r; asm("ex2.approx.f32 %0, %1;" : "=f"(r) : "f"(x)); return r;
}
__device__ __forceinline__ float rcp_approx(float x) {
    float r; asm("rcp.approx.f32 %0, %1;" : "=f"(r) : "f"(x)); return r;
}

// ---- f32x2 packed helpers (sm_103a FFMA2 path) ----
__device__ __forceinline__ uint64_t pk2(float a, float b) {
    uint64_t r; asm("mov.b64 %0, {%1, %2};" : "=l"(r) : "f"(a), "f"(b)); return r;
}
__device__ __forceinline__ float2 upk2(uint64_t p) {
    float2 v; asm("mov.b64 {%0, %1}, %2;" : "=f"(v.x), "=f"(v.y) : "l"(p)); return v;
}
__device__ __forceinline__ uint64_t f2fma(uint64_t a, uint64_t b, uint64_t c) {
    uint64_t r; asm("fma.rn.f32x2 %0, %1, %2, %3;" : "=l"(r) : "l"(a), "l"(b), "l"(c)); return r;
}
__device__ __forceinline__ uint64_t f2mul(uint64_t a, uint64_t b) {
    uint64_t r; asm("mul.rn.f32x2 %0, %1, %2;" : "=l"(r) : "l"(a), "l"(b)); return r;
}
__device__ __forceinline__ uint64_t f2add(uint64_t a, uint64_t b) {
    uint64_t r; asm("add.rn.f32x2 %0, %1, %2;" : "=l"(r) : "l"(a), "l"(b)); return r;
}
#define SGN2 0x8000000080000000ULL

struct GC { uint64_t c0, c1, one; };

// tanh-GELU, dual-lane: x - x*sigmoid(-arg) form via ex2+rcp.
__device__ __forceinline__ uint64_t gelu2t(uint64_t xp, const GC& k) {
    uint64_t x2  = f2mul(xp, xp);
    uint64_t wv  = f2fma(x2, k.c1, k.c0);
    uint64_t arg = f2mul(xp, wv);
    float2 av = upk2(arg);
    uint64_t e = pk2(ex2_approx(av.x), ex2_approx(av.y));
    float2 dv = upk2(f2add(e, k.one));
    uint64_t r = pk2(rcp_approx(dv.x), rcp_approx(dv.y));
    return f2fma(r ^ SGN2, xp, xp);   // x - x*r
}

__device__ __forceinline__ void mma16816(float (&c)[4],
    uint32_t a0, uint32_t a1, uint32_t a2, uint32_t a3, uint32_t b0, uint32_t b1) {
    asm volatile(
        "mma.sync.aligned.m16n8k16.row.col.f32.bf16.bf16.f32 "
        "{%0,%1,%2,%3}, {%4,%5,%6,%7}, {%8,%9}, {%0,%1,%2,%3};"
        : "+f"(c[0]), "+f"(c[1]), "+f"(c[2]), "+f"(c[3])
        : "r"(a0), "r"(a1), "r"(a2), "r"(a3), "r"(b0), "r"(b1));
}

__device__ __forceinline__ uint32_t packbf2(float lo, float hi) {
    __nv_bfloat162 h = __floats2bfloat162_rn(lo, hi);
    uint32_t u; memcpy(&u, &h, 4); return u;
}
__device__ __forceinline__ uint32_t cvtbf2(uint64_t p) {
    float2 v = upk2(p);
    uint32_t r;
    asm("cvt.rn.satfinite.bf16x2.f32 %0, %1, %2;" : "=r"(r) : "f"(v.y), "f"(v.x));
    return r;
}

__device__ __forceinline__ float blk_sum256(float v, float* sred, int t) {
    #pragma unroll
    for (int o = 16; o; o >>= 1) v += __shfl_xor_sync(0xffffffffu, v, o);
    __syncthreads();
    if ((t & 31) == 0) sred[t >> 5] = v;
    __syncthreads();
    float r = 0.f;
    #pragma unroll
    for (int w = 0; w < 8; w++) r += sred[w];
    return r;
}

// ---------- setup: blocks 0-31 exact ATT table; blocks 32-63 zero scratch + weight frags ----------
__global__ void setup_kernel(const float* __restrict__ qw1, const float* __restrict__ qb1,
                             const float* __restrict__ qg1, const float* __restrict__ qbt1,
                             const float* __restrict__ qw2, const float* __restrict__ qb2,
                             const float* __restrict__ qg2, const float* __restrict__ qbt2,
                             const float* __restrict__ qw3, const float* __restrict__ qb3,
                             const float* __restrict__ keys, const float* __restrict__ temperature,
                             const float* __restrict__ vw1, const float* __restrict__ vw2) {
    __shared__ float sh[256], sq[256], sred[8], ssim[32];
    int t = threadIdx.x, bidx = blockIdx.x;

    if (bidx >= 32) {
        int local = (bidx - 32) * 256 + t;      // 0..8191
        g_Sp[local] = 0.f;
        g_Sp[8192 + local] = 0.f;
        if (local < 8 * 32) g_cntp[local] = 0.f;
        if (local == 0) g_ctr = 0u;
        if (local < 2048) {
            int e = local & 1023, lane = e & 31, jk = e >> 5;
            int g = lane >> 2, i = lane & 3;
            if (local < 1024) {
                int j = jk >> 1, kp = jk & 1;
                int n = j * 8 + g;
                uint4 v;
                { int ks = 2*kp;   int c0 = ks*8+i, c1 = c0+4;
                  v.x = packbf2(vw1[(2*c0)*128+n], vw1[(2*c0+1)*128+n]);
                  v.y = packbf2(vw1[(2*c1)*128+n], vw1[(2*c1+1)*128+n]); }
                { int ks = 2*kp+1; int c0 = ks*8+i, c1 = c0+4;
                  v.z = packbf2(vw1[(2*c0)*128+n], vw1[(2*c0+1)*128+n]);
                  v.w = packbf2(vw1[(2*c1)*128+n], vw1[(2*c1+1)*128+n]); }
                g_w1f[e] = v;
            } else {
                int j = jk >> 2, kp = jk & 3;
                int n = j * 8 + g;
                uint4 v;
                { int ks = 2*kp;   int c0 = ks*8+i, c1 = c0+4;
                  v.x = packbf2(vw2[(2*c0)*64+n], vw2[(2*c0+1)*64+n]);
                  v.y = packbf2(vw2[(2*c1)*64+n], vw2[(2*c1+1)*64+n]); }
                { int ks = 2*kp+1; int c0 = ks*8+i, c1 = c0+4;
                  v.z = packbf2(vw2[(2*c0)*64+n], vw2[(2*c0+1)*64+n]);
                  v.w = packbf2(vw2[(2*c1)*64+n], vw2[(2*c1+1)*64+n]); }
                g_w2f[e] = v;
            }
        }
        return;
    }

    int idx = bidx;
    float v = 0.f;
    if (t < 128) {
        v = qb1[t];
        #pragma unroll
        for (int j = 0; j < 5; j++) v += (float)((idx >> j) & 1) * qw1[j * 128 + t];
    }
    float s1 = blk_sum256(v, sred, t);
    float s2 = blk_sum256(v * v, sred, t);
    if (t < 128) {
        float mean = s1 * (1.f / 128.f), var = s2 * (1.f / 128.f) - mean * mean;
        sh[t] = gelu_exact((v - mean) * rsqrtf(var + 1e-5f) * qg1[t] + qbt1[t]);
    }
    __syncthreads();
    float v2 = qb2[t];
    for (int k = 0; k < 128; k++) v2 += sh[k] * qw2[k * 256 + t];
    float s3 = blk_sum256(v2, sred, t);
    float s4 = blk_sum256(v2 * v2, sred, t);
    {
        float mean = s3 * (1.f / 256.f), var = s4 * (1.f / 256.f) - mean * mean;
        sh[t] = gelu_exact((v2 - mean) * rsqrtf(var + 1e-5f) * qg2[t] + qbt2[t]);
    }
    __syncthreads();
    float v3 = qb3[t];
    for (int k = 0; k < 256; k++) v3 += sh[k] * qw3[k * 256 + t];
    sq[t] = v3;
    float s5 = blk_sum256(v3 * v3, sred, t);
    float qnorm = fmaxf(sqrtf(s5), 1e-12f);
    int w = t >> 5, lane = t & 31;
    #pragma unroll
    for (int s = 0; s < 4; s++) {
        int n = w * 4 + s;
        float dot = 0.f, kn = 0.f;
        for (int d = lane; d < 256; d += 32) {
            float kv = keys[n * 256 + d];
            dot += sq[d] * kv; kn += kv * kv;
        }
        #pragma unroll
        for (int o = 16; o; o >>= 1) {
            dot += __shfl_xor_sync(0xffffffffu, dot, o);
            kn  += __shfl_xor_sync(0xffffffffu, kn, o);
        }
        if (lane == 0) ssim[n] = dot / (qnorm * fmaxf(sqrtf(kn), 1e-12f));
    }
    __syncthreads();
    if (t < 32) {
        float temp = fmaxf(fabsf(temperature[0]), 0.01f);
        float l = ssim[t] / temp, m = l;
        #pragma unroll
        for (int o = 16; o; o >>= 1) m = fmaxf(m, __shfl_xor_sync(0xffffffffu, m, o));
        float e = expf(l - m), ssum = e;
        #pragma unroll
        for (int o = 16; o; o >>= 1) ssum += __shfl_xor_sync(0xffffffffu, ssum, o);
        g_att[idx * 32 + t] = e / ssum;
    }
}

// ---------- enc v7: 512 threads; last CTA performs finalize in-kernel ----------
#define ENC_SMEM_BYTES 54144
__global__ void __launch_bounds__(512, 2) enc_kernel(
    const float* __restrict__ wval, const int* __restrict__ widx,
    const float* __restrict__ vb1, const float* __restrict__ vg1,
    const float* __restrict__ vbt1, const float* __restrict__ vb2,
    const float* __restrict__ regvals, const float* __restrict__ wstrength,
    float* __restrict__ out, int Btot) {
    extern __shared__ char smem[];
    uint32_t* sXu = (uint32_t*)(smem);
    float* sStats = (float*)(smem);
    __nv_bfloat16* sEt = (__nv_bfloat16*)(smem);       // stride 138 bf16 (69 u32)
    uint32_t* sEtu = (uint32_t*)(smem);
    uint4* sW1f = (uint4*)(smem + 18432);              // [1024]
    uint4* sW2f = (uint4*)(smem + 34816);              // [1024]
    float* sC2x = (float*)(smem + 18432);              // [8 pairs][1024]
    float* sSpart = (float*)(smem + 18432);            // [2][32][65]
    float* sVb1 = (float*)(smem + 51712);
    float* sVg1 = sVb1 + 128; float* sVbt1 = sVg1 + 128; float* sVb2 = sVbt1 + 128;
    int* sWidx = (int*)(smem + 53504);
    int* sCnt  = (int*)(smem + 54016);

    int tid = threadIdx.x, bid = blockIdx.x, rowbase = bid * 128;
    int w = tid >> 5, lane = tid & 31, g = lane >> 2, i = lane & 3;
    int mg = w >> 1, nh = w & 1;
    int r0 = mg * 16 + g;

    if (tid < 32) sCnt[tid] = 0;
    if (tid < 128) {
        sWidx[tid] = widx[rowbase + tid];
        sVb1[tid] = vb1[tid]; sVg1[tid] = vg1[tid]; sVbt1[tid] = vbt1[tid];
    }
    if (tid < 64) sVb2[tid] = vb2[tid];
    #pragma unroll
    for (int rep = 0; rep < 2; rep++) {
        int o = rep * 512 + tid;
        sW1f[o] = g_w1f[o];
        sW2f[o] = g_w2f[o];
    }
    __syncthreads();
    if (tid < 128) atomicAdd(&sCnt[sWidx[tid]], 1);
    {
        const float4* wv4 = (const float4*)wval;
        #pragma unroll
        for (int rep = 0; rep < 4; rep++) {
            int o = rep * 512 + tid, r = o >> 4, c = o & 15;
            float4 v = wv4[(size_t)(rowbase + r) * 16 + c];
            if (sWidx[r] == 31) { v.x = 0.f; v.y = 0.f; v.z = 0.f; v.w = 0.f; }
            uint2 u;
            u.x = packbf2(v.x, v.y);
            u.y = packbf2(v.z, v.w);
            *(uint2*)&sXu[r * 36 + 2 * c] = u;
        }
    }
    __syncthreads();

    // ---- layer 1 ----
    uint32_t A1[4][4];
    #pragma unroll
    for (int ks = 0; ks < 4; ks++) {
        int base = ks * 8 + i;
        A1[ks][0] = sXu[r0 * 36 + base];
        A1[ks][1] = sXu[(r0 + 8) * 36 + base];
        A1[ks][2] = sXu[r0 * 36 + base + 4];
        A1[ks][3] = sXu[(r0 + 8) * 36 + base + 4];
    }
    float C1[8][4];
    #pragma unroll
    for (int j = 0; j < 8; j++) C1[j][0] = C1[j][1] = C1[j][2] = C1[j][3] = 0.f;
    #pragma unroll
    for (int j = 0; j < 8; j++) {
        #pragma unroll
        for (int kp = 0; kp < 2; kp++) {
            uint4 b = sW1f[((nh * 8 + j) * 2 + kp) * 32 + lane];
            mma16816(C1[j], A1[2*kp][0], A1[2*kp][1], A1[2*kp][2], A1[2*kp][3], b.x, b.y);
            mma16816(C1[j], A1[2*kp+1][0], A1[2*kp+1][1], A1[2*kp+1][2], A1[2*kp+1][3], b.z, b.w);
        }
    }

    // ---- activation pipeline (f32x2) ----
    GC k;
    k.c0  = pk2(2.3022078f, 2.3022078f);
    k.c1  = pk2(0.10294326f, 0.10294326f);
    k.one = pk2(1.0f, 1.0f);

    uint64_t C1p[8][2];
    uint64_t acc0 = 0ull, accq0 = 0ull, acc1 = 0ull, accq1 = 0ull;
    #pragma unroll
    for (int j = 0; j < 8; j++) {
        uint64_t bb = *(const uint64_t*)&sVb1[nh * 64 + j * 8 + i * 2];
        uint64_t c01 = f2add(pk2(C1[j][0], C1[j][1]), bb);
        uint64_t c23 = f2add(pk2(C1[j][2], C1[j][3]), bb);
        C1p[j][0] = c01; C1p[j][1] = c23;
        acc0 = f2add(acc0, c01); accq0 = f2fma(c01, c01, accq0);
        acc1 = f2add(acc1, c23); accq1 = f2fma(c23, c23, accq1);
    }
    float2 a0v = upk2(acc0), q0v = upk2(accq0), a1v = upk2(acc1), q1v = upk2(accq1);
    float sum0 = a0v.x + a0v.y, sq0 = q0v.x + q0v.y;
    float sum1 = a1v.x + a1v.y, sq1 = q1v.x + q1v.y;
    #pragma unroll
    for (int o = 1; o <= 2; o <<= 1) {
        sum0 += __shfl_xor_sync(0xffffffffu, sum0, o);
        sq0  += __shfl_xor_sync(0xffffffffu, sq0, o);
        sum1 += __shfl_xor_sync(0xffffffffu, sum1, o);
        sq1  += __shfl_xor_sync(0xffffffffu, sq1, o);
    }
    __syncthreads();
    if (i == 0) {
        float4 st = make_float4(sum0, sq0, sum1, sq1);
        *(float4*)&sStats[(w * 8 + g) * 4] = st;
    }
    __syncthreads();
    {
        float4 oth = *(float4*)&sStats[((w ^ 1) * 8 + g) * 4];
        sum0 += oth.x; sq0 += oth.y; sum1 += oth.z; sq1 += oth.w;
    }
    float mean0 = sum0 * (1.f/128.f), var0 = sq0 * (1.f/128.f) - mean0*mean0;
    float mean1 = sum1 * (1.f/128.f), var1 = sq1 * (1.f/128.f) - mean1*mean1;
    float rs0 = rsqrtf(var0 + 1e-5f), rs1 = rsqrtf(var1 + 1e-5f);
    uint64_t rs0p = pk2(rs0, rs0), o0p = pk2(-mean0 * rs0, -mean0 * rs0);
    uint64_t rs1p = pk2(rs1, rs1), o1p = pk2(-mean1 * rs1, -mean1 * rs1);

    uint32_t A2[4][4];
    #pragma unroll
    for (int j = 0; j < 8; j++) {
        int c0 = nh * 64 + j * 8 + i * 2;
        uint64_t gg = *(const uint64_t*)&sVg1[c0];
        uint64_t tt = *(const uint64_t*)&sVbt1[c0];
        uint64_t v01 = f2fma(f2fma(C1p[j][0], rs0p, o0p), gg, tt);
        uint64_t v23 = f2fma(f2fma(C1p[j][1], rs1p, o1p), gg, tt);
        A2[j >> 1][(j & 1) * 2 + 0] = cvtbf2(gelu2t(v01, k));
        A2[j >> 1][(j & 1) * 2 + 1] = cvtbf2(gelu2t(v23, k));
    }

    // ---- layer 2 partial ----
    float C2[8][4];
    #pragma unroll
    for (int j = 0; j < 8; j++) C2[j][0] = C2[j][1] = C2[j][2] = C2[j][3] = 0.f;
    #pragma unroll
    for (int j = 0; j < 8; j++) {
        #pragma unroll
        for (int kpl = 0; kpl < 2; kpl++) {
            uint4 b = sW2f[(j * 4 + nh * 2 + kpl) * 32 + lane];
            mma16816(C2[j], A2[2*kpl][0], A2[2*kpl][1], A2[2*kpl][2], A2[2*kpl][3], b.x, b.y);
            mma16816(C2[j], A2[2*kpl+1][0], A2[2*kpl+1][1], A2[2*kpl+1][2], A2[2*kpl+1][3], b.z, b.w);
        }
    }
    __syncthreads();
    {
        float* xch = sC2x + mg * 1024;
        if (nh == 1) {
            #pragma unroll
            for (int j = 0; j < 8; j++)
                #pragma unroll
                for (int q = 0; q < 4; q++)
                    xch[(j * 4 + q) * 32 + lane] = C2[j][q];
        }
        __syncthreads();
        if (nh == 0) {
            #pragma unroll
            for (int j = 0; j < 8; j++)
                #pragma unroll
                for (int q = 0; q < 4; q++)
                    C2[j][q] += xch[(j * 4 + q) * 32 + lane];
            #pragma unroll
            for (int j = 0; j < 8; j++) {
                float2 bb = *(float2*)&sVb2[j * 8 + i * 2];
                C2[j][0] += bb.x; C2[j][1] += bb.y; C2[j][2] += bb.x; C2[j][3] += bb.y;
            }
            #pragma unroll
            for (int j = 0; j < 8; j++) {
                int c0 = j * 8 + i * 2;
                sEt[(c0    ) * 138 + r0    ] = __float2bfloat16(C2[j][0]);
                sEt[(c0 + 1) * 138 + r0    ] = __float2bfloat16(C2[j][1]);
                sEt[(c0    ) * 138 + r0 + 8] = __float2bfloat16(C2[j][2]);
                sEt[(c0 + 1) * 138 + r0 + 8] = __float2bfloat16(C2[j][3]);
            }
        }
    }
    __syncthreads();
    #pragma unroll
    for (int rep = 0; rep < 9; rep++) {
        int o = rep * 512 + tid;
        if (o < 2 * 32 * 65) sSpart[o] = 0.f;
    }
    __syncthreads();
    // ---- scatter MMA ----
    {
        int nq = w & 3, mh2 = (w >> 2) & 1, ksp = (w >> 3) & 1;
        float CS[2][4];
        #pragma unroll
        for (int j = 0; j < 2; j++) CS[j][0] = CS[j][1] = CS[j][2] = CS[j][3] = 0.f;
        #pragma unroll
        for (int ks2 = 0; ks2 < 4; ks2++) {
            int kb = ksp * 64 + ks2 * 16, k0 = kb + i * 2;
            int x0 = sWidx[k0], x1 = sWidx[k0 + 1], x2 = sWidx[k0 + 8], x3 = sWidx[k0 + 9];
            int mlo = mh2 * 16 + g, mhi = mlo + 8;
            uint32_t a0 = (x0 == mlo ? 0x3F80u : 0u) | (x1 == mlo ? 0x3F800000u : 0u);
            uint32_t a1 = (x0 == mhi ? 0x3F80u : 0u) | (x1 == mhi ? 0x3F800000u : 0u);
            uint32_t a2 = (x2 == mlo ? 0x3F80u : 0u) | (x3 == mlo ? 0x3F800000u : 0u);
            uint32_t a3 = (x2 == mhi ? 0x3F80u : 0u) | (x3 == mhi ? 0x3F800000u : 0u);
            #pragma unroll
            for (int j = 0; j < 2; j++) {
                int nrow = nq * 16 + j * 8 + g;
                mma16816(CS[j], a0, a1, a2, a3,
                         sEtu[nrow * 69 + (kb >> 1) + i], sEtu[nrow * 69 + (kb >> 1) + i + 4]);
            }
        }
        float* p = &sSpart[ksp * 2080];
        int m0 = mh2 * 16 + g;
        #pragma unroll
        for (int j = 0; j < 2; j++) {
            int c0 = nq * 16 + j * 8 + i * 2;
            p[m0 * 65 + c0]           = CS[j][0];
            p[m0 * 65 + c0 + 1]       = CS[j][1];
            p[(m0 + 8) * 65 + c0]     = CS[j][2];
            p[(m0 + 8) * 65 + c0 + 1] = CS[j][3];
        }
    }
    __syncthreads();
    int slice = bid & 7;
    #pragma unroll
    for (int rep = 0; rep < 4; rep++) {
        int o = rep * 512 + tid, m = o >> 6, c = o & 63;
        float v = sSpart[m * 65 + c] + sSpart[2080 + m * 65 + c];
        atomicAdd(&g_Sp[slice * 2048 + o], v);
    }
    if (tid < 32) atomicAdd(&g_cntp[slice * 32 + tid], (float)sCnt[tid]);

    // ---- last-CTA finalize (replaces separate kernel) ----
    __shared__ unsigned sIsLast;
    __threadfence();
    __syncthreads();            // all this CTA's atomics issued before the fence+count
    if (tid == 0) {
        unsigned old = atomicAdd(&g_ctr, 1u);
        sIsLast = (old == (unsigned)(gridDim.x - 1)) ? 1u : 0u;
    }
    __syncthreads();
    if (!sIsLast) return;

    // smem reuse for finalize (all prior regions dead)
    float* fS   = (float*)(smem);            // [2048]
    float* fATT = fS + 2048;                 // [1024]
    float* fNR  = fATT + 1024;               // [2048]
    float* fCnt = fNR + 2048;                // [32]
    float* fM   = fCnt + 32;                 // [32]

    #pragma unroll
    for (int rep = 0; rep < 4; rep++) {
        int o = rep * 512 + tid;
        float v = 0.f;
        #pragma unroll
        for (int sl = 0; sl < 8; sl++) v += g_Sp[sl * 2048 + o];
        fS[o] = v;
    }
    #pragma unroll
    for (int rep = 0; rep < 2; rep++) {
        int o = rep * 512 + tid;
        if (o < 1024) fATT[o] = g_att[o];
    }
    if (tid < 32) {
        float c = 0.f;
        #pragma unroll
        for (int sl = 0; sl < 8; sl++) c += g_cntp[sl * 32 + tid];
        fCnt[tid] = c;
    }
    __syncthreads();
    float invB = 1.f / (float)Btot;
    if (tid < 32) {
        float m = 0.f;
        for (int i2 = 0; i2 < 32; i2++) m += fCnt[i2] * invB * fATT[i2 * 32 + tid];
        fM[tid] = m;
    }
    __syncthreads();
    float s = 1.f / (1.f + expf(-wstrength[0]));
    #pragma unroll
    for (int rep = 0; rep < 4; rep++) {
        int o = rep * 512 + tid, n = o >> 6, d = o & 63;
        float as = 0.f;
        for (int i2 = 0; i2 < 32; i2++) as += fATT[i2 * 32 + n] * fS[i2 * 64 + d];
        float nr = (1.f - s * fM[n]) * regvals[o] + (s * invB) * as;
        out[(size_t)Btot * 64 + o] = nr;
        fNR[o] = nr;
    }
    __syncthreads();
    #pragma unroll
    for (int rep = 0; rep < 4; rep++) {
        int o = rep * 512 + tid, i2 = o >> 6, d = o & 63;
        float r = 0.f;
        for (int n = 0; n < 32; n++) r += fATT[i2 * 32 + n] * fNR[n * 64 + d];
        g_rout[o] = r;
    }
}

// ---------- read gather ----------
__global__ void __launch_bounds__(256) read_kernel(const int* __restrict__ ridx,
                                                   float* __restrict__ out) {
    __shared__ float4 sr[512];
    int t = threadIdx.x;
    #pragma unroll
    for (int rep = 0; rep < 2; rep++)
        sr[rep * 256 + t] = ((const float4*)g_rout)[rep * 256 + t];
    __syncthreads();
    int base = blockIdx.x * 128;
    #pragma unroll
    for (int it = 0; it < 8; it++) {
        int r = base + it * 16 + (t >> 4), cg = t & 15;
        int rv = ridx[r];
        float4 v = (rv == 31) ? make_float4(0.f, 0.f, 0.f, 0.f) : sr[rv * 16 + cg];
        ((float4*)out)[(size_t)r * 16 + cg] = v;
    }
}

// ---------- launcher ----------
extern "C" void kernel_launch(void* const* d_in, const int* in_sizes, int n_in,
                              void* d_out, int out_size) {
    const int*   wix  = (const int*)d_in[0];
    const float* wval = (const float*)d_in[1];
    const int*   rix  = (const int*)d_in[2];
    const float* regv = (const float*)d_in[3];
    const float* keys = (const float*)d_in[4];
    const float* qw1  = (const float*)d_in[5];
    const float* qb1  = (const float*)d_in[6];
    const float* qg1  = (const float*)d_in[7];
    const float* qbt1 = (const float*)d_in[8];
    const float* qw2  = (const float*)d_in[9];
    const float* qb2  = (const float*)d_in[10];
    const float* qg2  = (const float*)d_in[11];
    const float* qbt2 = (const float*)d_in[12];
    const float* qw3  = (const float*)d_in[13];
    const float* qb3  = (const float*)d_in[14];
    const float* vw1  = (const float*)d_in[15];
    const float* vb1  = (const float*)d_in[16];
    const float* vg1  = (const float*)d_in[17];
    const float* vbt1 = (const float*)d_in[18];
    const float* vw2  = (const float*)d_in[19];
    const float* vb2  = (const float*)d_in[20];
    const float* temp = (const float*)d_in[21];
    const float* wstr = (const float*)d_in[22];
    int B = in_sizes[0];

    cudaFuncSetAttribute(enc_kernel, cudaFuncAttributeMaxDynamicSharedMemorySize, ENC_SMEM_BYTES);

    setup_kernel<<<64, 256>>>(qw1, qb1, qg1, qbt1, qw2, qb2, qg2, qbt2, qw3, qb3,
                              keys, temp, vw1, vw2);
    enc_kernel<<<B / 128, 512, ENC_SMEM_BYTES>>>(wval, wix, vb1, vg1, vbt1, vb2,
                                                 regv, wstr, (float*)d_out, B);
    read_kernel<<<B / 128, 256>>>(rix, (float*)d_out);
}

// round 15
// speedup vs baseline: 1.2285x; 1.2285x over previous
#include <cuda_runtime.h>
#include <cuda_bf16.h>
#include <cstdint>
#include <cstring>

__device__ float g_att[32 * 32];
__device__ float g_Sp[8 * 2048];
__device__ float g_cntp[8 * 32];
__device__ float g_rout[2048];
__device__ uint4 g_w1f[32 * 32];   // layer1 B frags, 2 k-steps packed
__device__ uint4 g_w2f[32 * 32];   // layer2 B frags, 2 k-steps packed

__device__ __forceinline__ float gelu_exact(float x) {
    return 0.5f * x * (1.0f + erff(x * 0.7071067811865476f));
}
__device__ __forceinline__ float ex2_approx(float x) {
    float r; asm("ex2.approx.f32 %0, %1;" : "=f"(r) : "f"(x)); return r;
}
__device__ __forceinline__ float rcp_approx(float x) {
    float r; asm("rcp.approx.f32 %0, %1;" : "=f"(r) : "f"(x)); return r;
}

// ---- f32x2 packed helpers ----
__device__ __forceinline__ uint64_t pk2(float a, float b) {
    uint64_t r; asm("mov.b64 %0, {%1, %2};" : "=l"(r) : "f"(a), "f"(b)); return r;
}
__device__ __forceinline__ float2 upk2(uint64_t p) {
    float2 v; asm("mov.b64 {%0, %1}, %2;" : "=f"(v.x), "=f"(v.y) : "l"(p)); return v;
}
__device__ __forceinline__ uint64_t f2fma(uint64_t a, uint64_t b, uint64_t c) {
    uint64_t r; asm("fma.rn.f32x2 %0, %1, %2, %3;" : "=l"(r) : "l"(a), "l"(b), "l"(c)); return r;
}
__device__ __forceinline__ uint64_t f2mul(uint64_t a, uint64_t b) {
    uint64_t r; asm("mul.rn.f32x2 %0, %1, %2;" : "=l"(r) : "l"(a), "l"(b)); return r;
}
__device__ __forceinline__ uint64_t f2add(uint64_t a, uint64_t b) {
    uint64_t r; asm("add.rn.f32x2 %0, %1, %2;" : "=l"(r) : "l"(a), "l"(b)); return r;
}
#define SGN2 0x8000000080000000ULL

struct GC { uint64_t c0, c1, one; };

// tanh-GELU, dual-lane
__device__ __forceinline__ uint64_t gelu2t(uint64_t xp, const GC& k) {
    uint64_t x2  = f2mul(xp, xp);
    uint64_t wv  = f2fma(x2, k.c1, k.c0);
    uint64_t arg = f2mul(xp, wv);
    float2 av = upk2(arg);
    uint64_t e = pk2(ex2_approx(av.x), ex2_approx(av.y));
    float2 dv = upk2(f2add(e, k.one));
    uint64_t r = pk2(rcp_approx(dv.x), rcp_approx(dv.y));
    return f2fma(r ^ SGN2, xp, xp);
}

__device__ __forceinline__ void mma16816(float (&c)[4],
    uint32_t a0, uint32_t a1, uint32_t a2, uint32_t a3, uint32_t b0, uint32_t b1) {
    asm volatile(
        "mma.sync.aligned.m16n8k16.row.col.f32.bf16.bf16.f32 "
        "{%0,%1,%2,%3}, {%4,%5,%6,%7}, {%8,%9}, {%0,%1,%2,%3};"
        : "+f"(c[0]), "+f"(c[1]), "+f"(c[2]), "+f"(c[3])
        : "r"(a0), "r"(a1), "r"(a2), "r"(a3), "r"(b0), "r"(b1));
}

__device__ __forceinline__ uint32_t packbf2(float lo, float hi) {
    __nv_bfloat162 h = __floats2bfloat162_rn(lo, hi);
    uint32_t u; memcpy(&u, &h, 4); return u;
}
__device__ __forceinline__ uint32_t cvtbf2(uint64_t p) {
    float2 v = upk2(p);
    uint32_t r;
    asm("cvt.rn.satfinite.bf16x2.f32 %0, %1, %2;" : "=r"(r) : "f"(v.y), "f"(v.x));
    return r;
}

__device__ __forceinline__ float blk_sum1024(float v, float* sred, int t) {
    #pragma unroll
    for (int o = 16; o; o >>= 1) v += __shfl_xor_sync(0xffffffffu, v, o);
    __syncthreads();
    if ((t & 31) == 0) sred[t >> 5] = v;
    __syncthreads();
    float r = 0.f;
    #pragma unroll
    for (int w = 0; w < 32; w++) r += sred[w];
    return r;
}

// ---------- setup: blocks 0-31 ATT table (1024 thr, 4-way k-split); blocks 32-63 zero + weight frags ----------
__global__ void __launch_bounds__(1024) setup_kernel(
        const float* __restrict__ qw1, const float* __restrict__ qb1,
        const float* __restrict__ qg1, const float* __restrict__ qbt1,
        const float* __restrict__ qw2, const float* __restrict__ qb2,
        const float* __restrict__ qg2, const float* __restrict__ qbt2,
        const float* __restrict__ qw3, const float* __restrict__ qb3,
        const float* __restrict__ keys, const float* __restrict__ temperature,
        const float* __restrict__ vw1, const float* __restrict__ vw2) {
    __shared__ float sh[256], sh2[256], sq[256], sred[32], ssim[32];
    int t = threadIdx.x, bidx = blockIdx.x;

    if (bidx >= 32) {
        if (t < 256) {
            int local = (bidx - 32) * 256 + t;      // 0..8191
            g_Sp[local] = 0.f;
            g_Sp[8192 + local] = 0.f;
            if (local < 8 * 32) g_cntp[local] = 0.f;
            if (local < 2048) {
                int e = local & 1023, lane = e & 31, jk = e >> 5;
                int g = lane >> 2, i = lane & 3;
                if (local < 1024) {
                    int j = jk >> 1, kp = jk & 1;
                    int n = j * 8 + g;
                    uint4 v;
                    { int ks = 2*kp;   int c0 = ks*8+i, c1 = c0+4;
                      v.x = packbf2(vw1[(2*c0)*128+n], vw1[(2*c0+1)*128+n]);
                      v.y = packbf2(vw1[(2*c1)*128+n], vw1[(2*c1+1)*128+n]); }
                    { int ks = 2*kp+1; int c0 = ks*8+i, c1 = c0+4;
                      v.z = packbf2(vw1[(2*c0)*128+n], vw1[(2*c0+1)*128+n]);
                      v.w = packbf2(vw1[(2*c1)*128+n], vw1[(2*c1+1)*128+n]); }
                    g_w1f[e] = v;
                } else {
                    int j = jk >> 2, kp = jk & 3;
                    int n = j * 8 + g;
                    uint4 v;
                    { int ks = 2*kp;   int c0 = ks*8+i, c1 = c0+4;
                      v.x = packbf2(vw2[(2*c0)*64+n], vw2[(2*c0+1)*64+n]);
                      v.y = packbf2(vw2[(2*c1)*64+n], vw2[(2*c1+1)*64+n]); }
                    { int ks = 2*kp+1; int c0 = ks*8+i, c1 = c0+4;
                      v.z = packbf2(vw2[(2*c0)*64+n], vw2[(2*c0+1)*64+n]);
                      v.w = packbf2(vw2[(2*c1)*64+n], vw2[(2*c1+1)*64+n]); }
                    g_w2f[e] = v;
                }
            }
        }
        return;
    }

    // ---- exact ATT table for idx = bidx, 1024 threads ----
    int idx = bidx;
    // layer 1 (5 -> 128): threads < 128
    float v = 0.f;
    if (t < 128) {
        v = qb1[t];
        #pragma unroll
        for (int j = 0; j < 5; j++) v += (float)((idx >> j) & 1) * qw1[j * 128 + t];
    }
    float s1 = blk_sum1024(t < 128 ? v : 0.f, sred, t);
    float s2 = blk_sum1024(t < 128 ? v * v : 0.f, sred, t);
    if (t < 128) {
        float mean = s1 * (1.f / 128.f), var = s2 * (1.f / 128.f) - mean * mean;
        sh[t] = gelu_exact((v - mean) * rsqrtf(var + 1e-5f) * qg1[t] + qbt1[t]);
    }
    __syncthreads();

    // layer 2 (128 -> 256): col = t>>2, 4-way k-split
    int col = t >> 2, i4 = t & 3;
    float v2 = 0.f;
    {
        int k0 = i4 * 32;
        #pragma unroll 8
        for (int k = k0; k < k0 + 32; k++) v2 += sh[k] * qw2[k * 256 + col];
    }
    v2 += __shfl_xor_sync(0xffffffffu, v2, 1);
    v2 += __shfl_xor_sync(0xffffffffu, v2, 2);
    v2 += qb2[col];
    float s3 = blk_sum1024(i4 == 0 ? v2 : 0.f, sred, t);
    float s4 = blk_sum1024(i4 == 0 ? v2 * v2 : 0.f, sred, t);
    if (i4 == 0) {
        float mean = s3 * (1.f / 256.f), var = s4 * (1.f / 256.f) - mean * mean;
        sh2[col] = gelu_exact((v2 - mean) * rsqrtf(var + 1e-5f) * qg2[col] + qbt2[col]);
    }
    __syncthreads();

    // layer 3 (256 -> 256)
    float v3 = 0.f;
    {
        int k0 = i4 * 64;
        #pragma unroll 8
        for (int k = k0; k < k0 + 64; k++) v3 += sh2[k] * qw3[k * 256 + col];
    }
    v3 += __shfl_xor_sync(0xffffffffu, v3, 1);
    v3 += __shfl_xor_sync(0xffffffffu, v3, 2);
    v3 += qb3[col];
    if (i4 == 0) sq[col] = v3;
    float s5 = blk_sum1024(i4 == 0 ? v3 * v3 : 0.f, sred, t);
    float qnorm = fmaxf(sqrtf(s5), 1e-12f);

    // sims: warp w handles register n = w (32 warps)
    int w = t >> 5, lane = t & 31;
    {
        float dot = 0.f, kn = 0.f;
        #pragma unroll
        for (int d = lane; d < 256; d += 32) {
            float kv = keys[w * 256 + d];
            dot += sq[d] * kv; kn += kv * kv;
        }
        #pragma unroll
        for (int o = 16; o; o >>= 1) {
            dot += __shfl_xor_sync(0xffffffffu, dot, o);
            kn  += __shfl_xor_sync(0xffffffffu, kn, o);
        }
        if (lane == 0) ssim[w] = dot / (qnorm * fmaxf(sqrtf(kn), 1e-12f));
    }
    __syncthreads();
    if (t < 32) {
        float temp = fmaxf(fabsf(temperature[0]), 0.01f);
        float l = ssim[t] / temp, m = l;
        #pragma unroll
        for (int o = 16; o; o >>= 1) m = fmaxf(m, __shfl_xor_sync(0xffffffffu, m, o));
        float e = expf(l - m), ssum = e;
        #pragma unroll
        for (int o = 16; o; o >>= 1) ssum += __shfl_xor_sync(0xffffffffu, ssum, o);
        g_att[idx * 32 + t] = e / ssum;
    }
}

// ---------- enc v6 (R13): 512 threads, N-split pairs, f32x2 tanh-GELU ----------
#define ENC_SMEM_BYTES 54144
__global__ void __launch_bounds__(512, 2) enc_kernel(
    const float* __restrict__ wval, const int* __restrict__ widx,
    const float* __restrict__ vb1, const float* __restrict__ vg1,
    const float* __restrict__ vbt1, const float* __restrict__ vb2) {
    extern __shared__ char smem[];
    uint32_t* sXu = (uint32_t*)(smem);
    float* sStats = (float*)(smem);
    __nv_bfloat16* sEt = (__nv_bfloat16*)(smem);       // stride 138 bf16 (69 u32)
    uint32_t* sEtu = (uint32_t*)(smem);
    uint4* sW1f = (uint4*)(smem + 18432);              // [1024]
    uint4* sW2f = (uint4*)(smem + 34816);              // [1024]
    float* sC2x = (float*)(smem + 18432);              // [8 pairs][1024]
    float* sSpart = (float*)(smem + 18432);            // [2][32][65]
    float* sVb1 = (float*)(smem + 51712);
    float* sVg1 = sVb1 + 128; float* sVbt1 = sVg1 + 128; float* sVb2 = sVbt1 + 128;
    int* sWidx = (int*)(smem + 53504);
    int* sCnt  = (int*)(smem + 54016);

    int tid = threadIdx.x, bid = blockIdx.x, rowbase = bid * 128;
    int w = tid >> 5, lane = tid & 31, g = lane >> 2, i = lane & 3;
    int mg = w >> 1, nh = w & 1;
    int r0 = mg * 16 + g;

    if (tid < 32) sCnt[tid] = 0;
    if (tid < 128) {
        sWidx[tid] = widx[rowbase + tid];
        sVb1[tid] = vb1[tid]; sVg1[tid] = vg1[tid]; sVbt1[tid] = vbt1[tid];
    }
    if (tid < 64) sVb2[tid] = vb2[tid];
    #pragma unroll
    for (int rep = 0; rep < 2; rep++) {
        int o = rep * 512 + tid;
        sW1f[o] = g_w1f[o];
        sW2f[o] = g_w2f[o];
    }
    __syncthreads();
    if (tid < 128) atomicAdd(&sCnt[sWidx[tid]], 1);
    {
        const float4* wv4 = (const float4*)wval;
        #pragma unroll
        for (int rep = 0; rep < 4; rep++) {
            int o = rep * 512 + tid, r = o >> 4, c = o & 15;
            float4 v = wv4[(size_t)(rowbase + r) * 16 + c];
            if (sWidx[r] == 31) { v.x = 0.f; v.y = 0.f; v.z = 0.f; v.w = 0.f; }
            uint2 u;
            u.x = packbf2(v.x, v.y);
            u.y = packbf2(v.z, v.w);
            *(uint2*)&sXu[r * 36 + 2 * c] = u;
        }
    }
    __syncthreads();

    // ---- layer 1 ----
    uint32_t A1[4][4];
    #pragma unroll
    for (int ks = 0; ks < 4; ks++) {
        int base = ks * 8 + i;
        A1[ks][0] = sXu[r0 * 36 + base];
        A1[ks][1] = sXu[(r0 + 8) * 36 + base];
        A1[ks][2] = sXu[r0 * 36 + base + 4];
        A1[ks][3] = sXu[(r0 + 8) * 36 + base + 4];
    }
    float C1[8][4];
    #pragma unroll
    for (int j = 0; j < 8; j++) C1[j][0] = C1[j][1] = C1[j][2] = C1[j][3] = 0.f;
    #pragma unroll
    for (int j = 0; j < 8; j++) {
        #pragma unroll
        for (int kp = 0; kp < 2; kp++) {
            uint4 b = sW1f[((nh * 8 + j) * 2 + kp) * 32 + lane];
            mma16816(C1[j], A1[2*kp][0], A1[2*kp][1], A1[2*kp][2], A1[2*kp][3], b.x, b.y);
            mma16816(C1[j], A1[2*kp+1][0], A1[2*kp+1][1], A1[2*kp+1][2], A1[2*kp+1][3], b.z, b.w);
        }
    }

    // ---- activation pipeline (f32x2) ----
    GC k;
    k.c0  = pk2(2.3022078f, 2.3022078f);
    k.c1  = pk2(0.10294326f, 0.10294326f);
    k.one = pk2(1.0f, 1.0f);

    uint64_t C1p[8][2];
    uint64_t acc0 = 0ull, accq0 = 0ull, acc1 = 0ull, accq1 = 0ull;
    #pragma unroll
    for (int j = 0; j < 8; j++) {
        uint64_t bb = *(const uint64_t*)&sVb1[nh * 64 + j * 8 + i * 2];
        uint64_t c01 = f2add(pk2(C1[j][0], C1[j][1]), bb);
        uint64_t c23 = f2add(pk2(C1[j][2], C1[j][3]), bb);
        C1p[j][0] = c01; C1p[j][1] = c23;
        acc0 = f2add(acc0, c01); accq0 = f2fma(c01, c01, accq0);
        acc1 = f2add(acc1, c23); accq1 = f2fma(c23, c23, accq1);
    }
    float2 a0v = upk2(acc0), q0v = upk2(accq0), a1v = upk2(acc1), q1v = upk2(accq1);
    float sum0 = a0v.x + a0v.y, sq0 = q0v.x + q0v.y;
    float sum1 = a1v.x + a1v.y, sq1 = q1v.x + q1v.y;
    #pragma unroll
    for (int o = 1; o <= 2; o <<= 1) {
        sum0 += __shfl_xor_sync(0xffffffffu, sum0, o);
        sq0  += __shfl_xor_sync(0xffffffffu, sq0, o);
        sum1 += __shfl_xor_sync(0xffffffffu, sum1, o);
        sq1  += __shfl_xor_sync(0xffffffffu, sq1, o);
    }
    __syncthreads();
    if (i == 0) {
        float4 st = make_float4(sum0, sq0, sum1, sq1);
        *(float4*)&sStats[(w * 8 + g) * 4] = st;
    }
    __syncthreads();
    {
        float4 oth = *(float4*)&sStats[((w ^ 1) * 8 + g) * 4];
        sum0 += oth.x; sq0 += oth.y; sum1 += oth.z; sq1 += oth.w;
    }
    float mean0 = sum0 * (1.f/128.f), var0 = sq0 * (1.f/128.f) - mean0*mean0;
    float mean1 = sum1 * (1.f/128.f), var1 = sq1 * (1.f/128.f) - mean1*mean1;
    float rs0 = rsqrtf(var0 + 1e-5f), rs1 = rsqrtf(var1 + 1e-5f);
    uint64_t rs0p = pk2(rs0, rs0), o0p = pk2(-mean0 * rs0, -mean0 * rs0);
    uint64_t rs1p = pk2(rs1, rs1), o1p = pk2(-mean1 * rs1, -mean1 * rs1);

    uint32_t A2[4][4];
    #pragma unroll
    for (int j = 0; j < 8; j++) {
        int c0 = nh * 64 + j * 8 + i * 2;
        uint64_t gg = *(const uint64_t*)&sVg1[c0];
        uint64_t tt = *(const uint64_t*)&sVbt1[c0];
        uint64_t v01 = f2fma(f2fma(C1p[j][0], rs0p, o0p), gg, tt);
        uint64_t v23 = f2fma(f2fma(C1p[j][1], rs1p, o1p), gg, tt);
        A2[j >> 1][(j & 1) * 2 + 0] = cvtbf2(gelu2t(v01, k));
        A2[j >> 1][(j & 1) * 2 + 1] = cvtbf2(gelu2t(v23, k));
    }

    // ---- layer 2 partial ----
    float C2[8][4];
    #pragma unroll
    for (int j = 0; j < 8; j++) C2[j][0] = C2[j][1] = C2[j][2] = C2[j][3] = 0.f;
    #pragma unroll
    for (int j = 0; j < 8; j++) {
        #pragma unroll
        for (int kpl = 0; kpl < 2; kpl++) {
            uint4 b = sW2f[(j * 4 + nh * 2 + kpl) * 32 + lane];
            mma16816(C2[j], A2[2*kpl][0], A2[2*kpl][1], A2[2*kpl][2], A2[2*kpl][3], b.x, b.y);
            mma16816(C2[j], A2[2*kpl+1][0], A2[2*kpl+1][1], A2[2*kpl+1][2], A2[2*kpl+1][3], b.z, b.w);
        }
    }
    __syncthreads();
    {
        float* xch = sC2x + mg * 1024;
        if (nh == 1) {
            #pragma unroll
            for (int j = 0; j < 8; j++)
                #pragma unroll
                for (int q = 0; q < 4; q++)
                    xch[(j * 4 + q) * 32 + lane] = C2[j][q];
        }
        __syncthreads();
        if (nh == 0) {
            #pragma unroll
            for (int j = 0; j < 8; j++)
                #pragma unroll
                for (int q = 0; q < 4; q++)
                    C2[j][q] += xch[(j * 4 + q) * 32 + lane];
            #pragma unroll
            for (int j = 0; j < 8; j++) {
                float2 bb = *(float2*)&sVb2[j * 8 + i * 2];
                C2[j][0] += bb.x; C2[j][1] += bb.y; C2[j][2] += bb.x; C2[j][3] += bb.y;
            }
            #pragma unroll
            for (int j = 0; j < 8; j++) {
                int c0 = j * 8 + i * 2;
                sEt[(c0    ) * 138 + r0    ] = __float2bfloat16(C2[j][0]);
                sEt[(c0 + 1) * 138 + r0    ] = __float2bfloat16(C2[j][1]);
                sEt[(c0    ) * 138 + r0 + 8] = __float2bfloat16(C2[j][2]);
                sEt[(c0 + 1) * 138 + r0 + 8] = __float2bfloat16(C2[j][3]);
            }
        }
    }
    __syncthreads();
    #pragma unroll
    for (int rep = 0; rep < 9; rep++) {
        int o = rep * 512 + tid;
        if (o < 2 * 32 * 65) sSpart[o] = 0.f;
    }
    __syncthreads();
    // ---- scatter MMA: 2-way k x 2-way m x 4-way n ----
    {
        int nq = w & 3, mh2 = (w >> 2) & 1, ksp = (w >> 3) & 1;
        float CS[2][4];
        #pragma unroll
        for (int j = 0; j < 2; j++) CS[j][0] = CS[j][1] = CS[j][2] = CS[j][3] = 0.f;
        #pragma unroll
        for (int ks2 = 0; ks2 < 4; ks2++) {
            int kb = ksp * 64 + ks2 * 16, k0 = kb + i * 2;
            int x0 = sWidx[k0], x1 = sWidx[k0 + 1], x2 = sWidx[k0 + 8], x3 = sWidx[k0 + 9];
            int mlo = mh2 * 16 + g, mhi = mlo + 8;
            uint32_t a0 = (x0 == mlo ? 0x3F80u : 0u) | (x1 == mlo ? 0x3F800000u : 0u);
            uint32_t a1 = (x0 == mhi ? 0x3F80u : 0u) | (x1 == mhi ? 0x3F800000u : 0u);
            uint32_t a2 = (x2 == mlo ? 0x3F80u : 0u) | (x3 == mlo ? 0x3F800000u : 0u);
            uint32_t a3 = (x2 == mhi ? 0x3F80u : 0u) | (x3 == mhi ? 0x3F800000u : 0u);
            #pragma unroll
            for (int j = 0; j < 2; j++) {
                int nrow = nq * 16 + j * 8 + g;
                mma16816(CS[j], a0, a1, a2, a3,
                         sEtu[nrow * 69 + (kb >> 1) + i], sEtu[nrow * 69 + (kb >> 1) + i + 4]);
            }
        }
        float* p = &sSpart[ksp * 2080];
        int m0 = mh2 * 16 + g;
        #pragma unroll
        for (int j = 0; j < 2; j++) {
            int c0 = nq * 16 + j * 8 + i * 2;
            p[m0 * 65 + c0]           = CS[j][0];
            p[m0 * 65 + c0 + 1]       = CS[j][1];
            p[(m0 + 8) * 65 + c0]     = CS[j][2];
            p[(m0 + 8) * 65 + c0 + 1] = CS[j][3];
        }
    }
    __syncthreads();
    int slice = bid & 7;
    #pragma unroll
    for (int rep = 0; rep < 4; rep++) {
        int o = rep * 512 + tid, m = o >> 6, c = o & 63;
        float v = sSpart[m * 65 + c] + sSpart[2080 + m * 65 + c];
        atomicAdd(&g_Sp[slice * 2048 + o], v);
    }
    if (tid < 32) atomicAdd(&g_cntp[slice * 32 + tid], (float)sCnt[tid]);
}

// ---------- finalize: slice reduce + new_regs + ROUT ----------
__global__ void finalize_kernel(const float* __restrict__ regvals,
                                const float* __restrict__ wstrength,
                                float* __restrict__ out, int Btot) {
    __shared__ float sS[2048], sATT[1024], sCnt[32], sM[32], sNR[2048];
    int t = threadIdx.x;  // 1024
    sATT[t] = g_att[t];
    #pragma unroll
    for (int rep = 0; rep < 2; rep++) {
        int o = rep * 1024 + t;
        float v = 0.f;
        #pragma unroll
        for (int sl = 0; sl < 8; sl++) v += g_Sp[sl * 2048 + o];
        sS[o] = v;
    }
    if (t < 32) {
        float c = 0.f;
        #pragma unroll
        for (int sl = 0; sl < 8; sl++) c += g_cntp[sl * 32 + t];
        sCnt[t] = c;
    }
    __syncthreads();
    float invB = 1.f / (float)Btot;
    if (t < 32) {
        float m = 0.f;
        for (int i2 = 0; i2 < 32; i2++) m += sCnt[i2] * invB * sATT[i2 * 32 + t];
        sM[t] = m;
    }
    __syncthreads();
    float s = 1.f / (1.f + expf(-wstrength[0]));
    #pragma unroll
    for (int rep = 0; rep < 2; rep++) {
        int o = rep * 1024 + t, n = o >> 6, d = o & 63;
        float as = 0.f;
        for (int i2 = 0; i2 < 32; i2++) as += sATT[i2 * 32 + n] * sS[i2 * 64 + d];
        float nr = (1.f - s * sM[n]) * regvals[o] + (s * invB) * as;
        out[(size_t)Btot * 64 + o] = nr;
        sNR[o] = nr;
    }
    __syncthreads();
    #pragma unroll
    for (int rep = 0; rep < 2; rep++) {
        int o = rep * 1024 + t, i2 = o >> 6, d = o & 63;
        float r = 0.f;
        for (int n = 0; n < 32; n++) r += sATT[i2 * 32 + n] * sNR[n * 64 + d];
        g_rout[o] = r;
    }
}

// ---------- read gather ----------
__global__ void __launch_bounds__(256) read_kernel(const int* __restrict__ ridx,
                                                   float* __restrict__ out) {
    __shared__ float4 sr[512];
    int t = threadIdx.x;
    #pragma unroll
    for (int rep = 0; rep < 2; rep++)
        sr[rep * 256 + t] = ((const float4*)g_rout)[rep * 256 + t];
    __syncthreads();
    int base = blockIdx.x * 128;
    #pragma unroll
    for (int it = 0; it < 8; it++) {
        int r = base + it * 16 + (t >> 4), cg = t & 15;
        int rv = ridx[r];
        float4 v = (rv == 31) ? make_float4(0.f, 0.f, 0.f, 0.f) : sr[rv * 16 + cg];
        ((float4*)out)[(size_t)r * 16 + cg] = v;
    }
}

// ---------- launcher ----------
extern "C" void kernel_launch(void* const* d_in, const int* in_sizes, int n_in,
                              void* d_out, int out_size) {
    const int*   wix  = (const int*)d_in[0];
    const float* wval = (const float*)d_in[1];
    const int*   rix  = (const int*)d_in[2];
    const float* regv = (const float*)d_in[3];
    const float* keys = (const float*)d_in[4];
    const float* qw1  = (const float*)d_in[5];
    const float* qb1  = (const float*)d_in[6];
    const float* qg1  = (const float*)d_in[7];
    const float* qbt1 = (const float*)d_in[8];
    const float* qw2  = (const float*)d_in[9];
    const float* qb2  = (const float*)d_in[10];
    const float* qg2  = (const float*)d_in[11];
    const float* qbt2 = (const float*)d_in[12];
    const float* qw3  = (const float*)d_in[13];
    const float* qb3  = (const float*)d_in[14];
    const float* vw1  = (const float*)d_in[15];
    const float* vb1  = (const float*)d_in[16];
    const float* vg1  = (const float*)d_in[17];
    const float* vbt1 = (const float*)d_in[18];
    const float* vw2  = (const float*)d_in[19];
    const float* vb2  = (const float*)d_in[20];
    const float* temp = (const float*)d_in[21];
    const float* wstr = (const float*)d_in[22];
    int B = in_sizes[0];

    cudaFuncSetAttribute(enc_kernel, cudaFuncAttributeMaxDynamicSharedMemorySize, ENC_SMEM_BYTES);

    setup_kernel<<<64, 1024>>>(qw1, qb1, qg1, qbt1, qw2, qb2, qg2, qbt2, qw3, qb3,
                               keys, temp, vw1, vw2);
    enc_kernel<<<B / 128, 512, ENC_SMEM_BYTES>>>(wval, wix, vb1, vg1, vbt1, vb2);
    finalize_kernel<<<1, 1024>>>(regv, wstr, (float*)d_out, B);
    read_kernel<<<B / 128, 256>>>(rix, (float*)d_out);
}

// round 16
// speedup vs baseline: 1.2331x; 1.0038x over previous
#include <cuda_runtime.h>
#include <cuda_bf16.h>
#include <cstdint>
#include <cstring>

__device__ float g_att[32 * 32];
__device__ float g_Sp[8 * 2048];
__device__ float g_cntp[8 * 32];
__device__ float g_rout[2048];
__device__ uint4 g_w1f[32 * 32];   // layer1 B frags, 2 k-steps packed
__device__ uint4 g_w2f[32 * 32];   // layer2 B frags, 2 k-steps packed

__device__ __forceinline__ float gelu_exact(float x) {
    return 0.5f * x * (1.0f + erff(x * 0.7071067811865476f));
}
__device__ __forceinline__ float ex2_approx(float x) {
    float r; asm("ex2.approx.f32 %0, %1;" : "=f"(r) : "f"(x)); return r;
}
__device__ __forceinline__ float rcp_approx(float x) {
    float r; asm("rcp.approx.f32 %0, %1;" : "=f"(r) : "f"(x)); return r;
}

// ---- f32x2 packed helpers ----
__device__ __forceinline__ uint64_t pk2(float a, float b) {
    uint64_t r; asm("mov.b64 %0, {%1, %2};" : "=l"(r) : "f"(a), "f"(b)); return r;
}
__device__ __forceinline__ float2 upk2(uint64_t p) {
    float2 v; asm("mov.b64 {%0, %1}, %2;" : "=f"(v.x), "=f"(v.y) : "l"(p)); return v;
}
__device__ __forceinline__ uint64_t f2fma(uint64_t a, uint64_t b, uint64_t c) {
    uint64_t r; asm("fma.rn.f32x2 %0, %1, %2, %3;" : "=l"(r) : "l"(a), "l"(b), "l"(c)); return r;
}
__device__ __forceinline__ uint64_t f2mul(uint64_t a, uint64_t b) {
    uint64_t r; asm("mul.rn.f32x2 %0, %1, %2;" : "=l"(r) : "l"(a), "l"(b)); return r;
}
__device__ __forceinline__ uint64_t f2add(uint64_t a, uint64_t b) {
    uint64_t r; asm("add.rn.f32x2 %0, %1, %2;" : "=l"(r) : "l"(a), "l"(b)); return r;
}
#define SGN2 0x8000000080000000ULL

struct GC { uint64_t c0, c1, one; };

// tanh-GELU, dual-lane
__device__ __forceinline__ uint64_t gelu2t(uint64_t xp, const GC& k) {
    uint64_t x2  = f2mul(xp, xp);
    uint64_t wv  = f2fma(x2, k.c1, k.c0);
    uint64_t arg = f2mul(xp, wv);
    float2 av = upk2(arg);
    uint64_t e = pk2(ex2_approx(av.x), ex2_approx(av.y));
    float2 dv = upk2(f2add(e, k.one));
    uint64_t r = pk2(rcp_approx(dv.x), rcp_approx(dv.y));
    return f2fma(r ^ SGN2, xp, xp);
}

__device__ __forceinline__ void mma16816(float (&c)[4],
    uint32_t a0, uint32_t a1, uint32_t a2, uint32_t a3, uint32_t b0, uint32_t b1) {
    asm volatile(
        "mma.sync.aligned.m16n8k16.row.col.f32.bf16.bf16.f32 "
        "{%0,%1,%2,%3}, {%4,%5,%6,%7}, {%8,%9}, {%0,%1,%2,%3};"
        : "+f"(c[0]), "+f"(c[1]), "+f"(c[2]), "+f"(c[3])
        : "r"(a0), "r"(a1), "r"(a2), "r"(a3), "r"(b0), "r"(b1));
}

__device__ __forceinline__ uint32_t packbf2(float lo, float hi) {
    __nv_bfloat162 h = __floats2bfloat162_rn(lo, hi);
    uint32_t u; memcpy(&u, &h, 4); return u;
}
__device__ __forceinline__ uint32_t cvtbf2(uint64_t p) {
    float2 v = upk2(p);
    uint32_t r;
    asm("cvt.rn.satfinite.bf16x2.f32 %0, %1, %2;" : "=r"(r) : "f"(v.y), "f"(v.x));
    return r;
}

__device__ __forceinline__ float blk_sum1024(float v, float* sred, int t) {
    #pragma unroll
    for (int o = 16; o; o >>= 1) v += __shfl_xor_sync(0xffffffffu, v, o);
    __syncthreads();
    if ((t & 31) == 0) sred[t >> 5] = v;
    __syncthreads();
    float r = 0.f;
    #pragma unroll
    for (int w = 0; w < 32; w++) r += sred[w];
    return r;
}

// ---------- setup: blocks 0-31 ATT table (1024 thr, 4-way k-split); blocks 32-63 zero + weight frags ----------
__global__ void __launch_bounds__(1024) setup_kernel(
        const float* __restrict__ qw1, const float* __restrict__ qb1,
        const float* __restrict__ qg1, const float* __restrict__ qbt1,
        const float* __restrict__ qw2, const float* __restrict__ qb2,
        const float* __restrict__ qg2, const float* __restrict__ qbt2,
        const float* __restrict__ qw3, const float* __restrict__ qb3,
        const float* __restrict__ keys, const float* __restrict__ temperature,
        const float* __restrict__ vw1, const float* __restrict__ vw2) {
    __shared__ float sh[256], sh2[256], sq[256], sred[32], ssim[32];
    int t = threadIdx.x, bidx = blockIdx.x;

    if (bidx >= 32) {
        if (t < 256) {
            int local = (bidx - 32) * 256 + t;      // 0..8191
            g_Sp[local] = 0.f;
            g_Sp[8192 + local] = 0.f;
            if (local < 8 * 32) g_cntp[local] = 0.f;
            if (local < 2048) {
                int e = local & 1023, lane = e & 31, jk = e >> 5;
                int g = lane >> 2, i = lane & 3;
                if (local < 1024) {
                    int j = jk >> 1, kp = jk & 1;
                    int n = j * 8 + g;
                    uint4 v;
                    { int ks = 2*kp;   int c0 = ks*8+i, c1 = c0+4;
                      v.x = packbf2(vw1[(2*c0)*128+n], vw1[(2*c0+1)*128+n]);
                      v.y = packbf2(vw1[(2*c1)*128+n], vw1[(2*c1+1)*128+n]); }
                    { int ks = 2*kp+1; int c0 = ks*8+i, c1 = c0+4;
                      v.z = packbf2(vw1[(2*c0)*128+n], vw1[(2*c0+1)*128+n]);
                      v.w = packbf2(vw1[(2*c1)*128+n], vw1[(2*c1+1)*128+n]); }
                    g_w1f[e] = v;
                } else {
                    int j = jk >> 2, kp = jk & 3;
                    int n = j * 8 + g;
                    uint4 v;
                    { int ks = 2*kp;   int c0 = ks*8+i, c1 = c0+4;
                      v.x = packbf2(vw2[(2*c0)*64+n], vw2[(2*c0+1)*64+n]);
                      v.y = packbf2(vw2[(2*c1)*64+n], vw2[(2*c1+1)*64+n]); }
                    { int ks = 2*kp+1; int c0 = ks*8+i, c1 = c0+4;
                      v.z = packbf2(vw2[(2*c0)*64+n], vw2[(2*c0+1)*64+n]);
                      v.w = packbf2(vw2[(2*c1)*64+n], vw2[(2*c1+1)*64+n]); }
                    g_w2f[e] = v;
                }
            }
        }
        return;
    }

    // ---- exact ATT table for idx = bidx, 1024 threads ----
    int idx = bidx;
    float v = 0.f;
    if (t < 128) {
        v = qb1[t];
        #pragma unroll
        for (int j = 0; j < 5; j++) v += (float)((idx >> j) & 1) * qw1[j * 128 + t];
    }
    float s1 = blk_sum1024(t < 128 ? v : 0.f, sred, t);
    float s2 = blk_sum1024(t < 128 ? v * v : 0.f, sred, t);
    if (t < 128) {
        float mean = s1 * (1.f / 128.f), var = s2 * (1.f / 128.f) - mean * mean;
        sh[t] = gelu_exact((v - mean) * rsqrtf(var + 1e-5f) * qg1[t] + qbt1[t]);
    }
    __syncthreads();

    int col = t >> 2, i4 = t & 3;
    float v2 = 0.f;
    {
        int k0 = i4 * 32;
        #pragma unroll 8
        for (int k = k0; k < k0 + 32; k++) v2 += sh[k] * qw2[k * 256 + col];
    }
    v2 += __shfl_xor_sync(0xffffffffu, v2, 1);
    v2 += __shfl_xor_sync(0xffffffffu, v2, 2);
    v2 += qb2[col];
    float s3 = blk_sum1024(i4 == 0 ? v2 : 0.f, sred, t);
    float s4 = blk_sum1024(i4 == 0 ? v2 * v2 : 0.f, sred, t);
    if (i4 == 0) {
        float mean = s3 * (1.f / 256.f), var = s4 * (1.f / 256.f) - mean * mean;
        sh2[col] = gelu_exact((v2 - mean) * rsqrtf(var + 1e-5f) * qg2[col] + qbt2[col]);
    }
    __syncthreads();

    float v3 = 0.f;
    {
        int k0 = i4 * 64;
        #pragma unroll 8
        for (int k = k0; k < k0 + 64; k++) v3 += sh2[k] * qw3[k * 256 + col];
    }
    v3 += __shfl_xor_sync(0xffffffffu, v3, 1);
    v3 += __shfl_xor_sync(0xffffffffu, v3, 2);
    v3 += qb3[col];
    if (i4 == 0) sq[col] = v3;
    float s5 = blk_sum1024(i4 == 0 ? v3 * v3 : 0.f, sred, t);
    float qnorm = fmaxf(sqrtf(s5), 1e-12f);

    int w = t >> 5, lane = t & 31;
    {
        float dot = 0.f, kn = 0.f;
        #pragma unroll
        for (int d = lane; d < 256; d += 32) {
            float kv = keys[w * 256 + d];
            dot += sq[d] * kv; kn += kv * kv;
        }
        #pragma unroll
        for (int o = 16; o; o >>= 1) {
            dot += __shfl_xor_sync(0xffffffffu, dot, o);
            kn  += __shfl_xor_sync(0xffffffffu, kn, o);
        }
        if (lane == 0) ssim[w] = dot / (qnorm * fmaxf(sqrtf(kn), 1e-12f));
    }
    __syncthreads();
    if (t < 32) {
        float temp = fmaxf(fabsf(temperature[0]), 0.01f);
        float l = ssim[t] / temp, m = l;
        #pragma unroll
        for (int o = 16; o; o >>= 1) m = fmaxf(m, __shfl_xor_sync(0xffffffffu, m, o));
        float e = expf(l - m), ssum = e;
        #pragma unroll
        for (int o = 16; o; o >>= 1) ssum += __shfl_xor_sync(0xffffffffu, ssum, o);
        g_att[idx * 32 + t] = e / ssum;
    }
}

// ---------- enc v6: 512 threads, N-split pairs, f32x2 tanh-GELU ----------
#define ENC_SMEM_BYTES 54144
__global__ void __launch_bounds__(512, 2) enc_kernel(
    const float* __restrict__ wval, const int* __restrict__ widx,
    const float* __restrict__ vb1, const float* __restrict__ vg1,
    const float* __restrict__ vbt1, const float* __restrict__ vb2) {
    extern __shared__ char smem[];
    uint32_t* sXu = (uint32_t*)(smem);
    float* sStats = (float*)(smem);
    __nv_bfloat16* sEt = (__nv_bfloat16*)(smem);       // stride 138 bf16 (69 u32)
    uint32_t* sEtu = (uint32_t*)(smem);
    uint4* sW1f = (uint4*)(smem + 18432);              // [1024]
    uint4* sW2f = (uint4*)(smem + 34816);              // [1024]
    float* sC2x = (float*)(smem + 18432);              // [8 pairs][1024]
    float* sSpart = (float*)(smem + 18432);            // [2][32][65]
    float* sVb1 = (float*)(smem + 51712);
    float* sVg1 = sVb1 + 128; float* sVbt1 = sVg1 + 128; float* sVb2 = sVbt1 + 128;
    int* sWidx = (int*)(smem + 53504);
    int* sCnt  = (int*)(smem + 54016);

    int tid = threadIdx.x, bid = blockIdx.x, rowbase = bid * 128;
    int w = tid >> 5, lane = tid & 31, g = lane >> 2, i = lane & 3;
    int mg = w >> 1, nh = w & 1;
    int r0 = mg * 16 + g;

    if (tid < 32) sCnt[tid] = 0;
    if (tid < 128) {
        sWidx[tid] = widx[rowbase + tid];
        sVb1[tid] = vb1[tid]; sVg1[tid] = vg1[tid]; sVbt1[tid] = vbt1[tid];
    }
    if (tid < 64) sVb2[tid] = vb2[tid];
    #pragma unroll
    for (int rep = 0; rep < 2; rep++) {
        int o = rep * 512 + tid;
        sW1f[o] = g_w1f[o];
        sW2f[o] = g_w2f[o];
    }
    __syncthreads();
    if (tid < 128) atomicAdd(&sCnt[sWidx[tid]], 1);
    {
        const float4* wv4 = (const float4*)wval;
        #pragma unroll
        for (int rep = 0; rep < 4; rep++) {
            int o = rep * 512 + tid, r = o >> 4, c = o & 15;
            float4 v = wv4[(size_t)(rowbase + r) * 16 + c];
            if (sWidx[r] == 31) { v.x = 0.f; v.y = 0.f; v.z = 0.f; v.w = 0.f; }
            uint2 u;
            u.x = packbf2(v.x, v.y);
            u.y = packbf2(v.z, v.w);
            *(uint2*)&sXu[r * 36 + 2 * c] = u;
        }
    }
    __syncthreads();

    // ---- layer 1 ----
    uint32_t A1[4][4];
    #pragma unroll
    for (int ks = 0; ks < 4; ks++) {
        int base = ks * 8 + i;
        A1[ks][0] = sXu[r0 * 36 + base];
        A1[ks][1] = sXu[(r0 + 8) * 36 + base];
        A1[ks][2] = sXu[r0 * 36 + base + 4];
        A1[ks][3] = sXu[(r0 + 8) * 36 + base + 4];
    }
    float C1[8][4];
    #pragma unroll
    for (int j = 0; j < 8; j++) C1[j][0] = C1[j][1] = C1[j][2] = C1[j][3] = 0.f;
    #pragma unroll
    for (int j = 0; j < 8; j++) {
        #pragma unroll
        for (int kp = 0; kp < 2; kp++) {
            uint4 b = sW1f[((nh * 8 + j) * 2 + kp) * 32 + lane];
            mma16816(C1[j], A1[2*kp][0], A1[2*kp][1], A1[2*kp][2], A1[2*kp][3], b.x, b.y);
            mma16816(C1[j], A1[2*kp+1][0], A1[2*kp+1][1], A1[2*kp+1][2], A1[2*kp+1][3], b.z, b.w);
        }
    }

    // ---- activation pipeline (f32x2) ----
    GC k;
    k.c0  = pk2(2.3022078f, 2.3022078f);
    k.c1  = pk2(0.10294326f, 0.10294326f);
    k.one = pk2(1.0f, 1.0f);

    uint64_t C1p[8][2];
    uint64_t acc0 = 0ull, accq0 = 0ull, acc1 = 0ull, accq1 = 0ull;
    #pragma unroll
    for (int j = 0; j < 8; j++) {
        uint64_t bb = *(const uint64_t*)&sVb1[nh * 64 + j * 8 + i * 2];
        uint64_t c01 = f2add(pk2(C1[j][0], C1[j][1]), bb);
        uint64_t c23 = f2add(pk2(C1[j][2], C1[j][3]), bb);
        C1p[j][0] = c01; C1p[j][1] = c23;
        acc0 = f2add(acc0, c01); accq0 = f2fma(c01, c01, accq0);
        acc1 = f2add(acc1, c23); accq1 = f2fma(c23, c23, accq1);
    }
    float2 a0v = upk2(acc0), q0v = upk2(accq0), a1v = upk2(acc1), q1v = upk2(accq1);
    float sum0 = a0v.x + a0v.y, sq0 = q0v.x + q0v.y;
    float sum1 = a1v.x + a1v.y, sq1 = q1v.x + q1v.y;
    #pragma unroll
    for (int o = 1; o <= 2; o <<= 1) {
        sum0 += __shfl_xor_sync(0xffffffffu, sum0, o);
        sq0  += __shfl_xor_sync(0xffffffffu, sq0, o);
        sum1 += __shfl_xor_sync(0xffffffffu, sum1, o);
        sq1  += __shfl_xor_sync(0xffffffffu, sq1, o);
    }
    __syncthreads();
    if (i == 0) {
        float4 st = make_float4(sum0, sq0, sum1, sq1);
        *(float4*)&sStats[(w * 8 + g) * 4] = st;
    }
    __syncthreads();
    {
        float4 oth = *(float4*)&sStats[((w ^ 1) * 8 + g) * 4];
        sum0 += oth.x; sq0 += oth.y; sum1 += oth.z; sq1 += oth.w;
    }
    float mean0 = sum0 * (1.f/128.f), var0 = sq0 * (1.f/128.f) - mean0*mean0;
    float mean1 = sum1 * (1.f/128.f), var1 = sq1 * (1.f/128.f) - mean1*mean1;
    float rs0 = rsqrtf(var0 + 1e-5f), rs1 = rsqrtf(var1 + 1e-5f);
    uint64_t rs0p = pk2(rs0, rs0), o0p = pk2(-mean0 * rs0, -mean0 * rs0);
    uint64_t rs1p = pk2(rs1, rs1), o1p = pk2(-mean1 * rs1, -mean1 * rs1);

    uint32_t A2[4][4];
    #pragma unroll
    for (int j = 0; j < 8; j++) {
        int c0 = nh * 64 + j * 8 + i * 2;
        uint64_t gg = *(const uint64_t*)&sVg1[c0];
        uint64_t tt = *(const uint64_t*)&sVbt1[c0];
        uint64_t v01 = f2fma(f2fma(C1p[j][0], rs0p, o0p), gg, tt);
        uint64_t v23 = f2fma(f2fma(C1p[j][1], rs1p, o1p), gg, tt);
        A2[j >> 1][(j & 1) * 2 + 0] = cvtbf2(gelu2t(v01, k));
        A2[j >> 1][(j & 1) * 2 + 1] = cvtbf2(gelu2t(v23, k));
    }

    // ---- layer 2 partial ----
    float C2[8][4];
    #pragma unroll
    for (int j = 0; j < 8; j++) C2[j][0] = C2[j][1] = C2[j][2] = C2[j][3] = 0.f;
    #pragma unroll
    for (int j = 0; j < 8; j++) {
        #pragma unroll
        for (int kpl = 0; kpl < 2; kpl++) {
            uint4 b = sW2f[(j * 4 + nh * 2 + kpl) * 32 + lane];
            mma16816(C2[j], A2[2*kpl][0], A2[2*kpl][1], A2[2*kpl][2], A2[2*kpl][3], b.x, b.y);
            mma16816(C2[j], A2[2*kpl+1][0], A2[2*kpl+1][1], A2[2*kpl+1][2], A2[2*kpl+1][3], b.z, b.w);
        }
    }
    __syncthreads();
    {
        float* xch = sC2x + mg * 1024;
        if (nh == 1) {
            #pragma unroll
            for (int j = 0; j < 8; j++)
                #pragma unroll
                for (int q = 0; q < 4; q++)
                    xch[(j * 4 + q) * 32 + lane] = C2[j][q];
        }
        __syncthreads();
        if (nh == 0) {
            #pragma unroll
            for (int j = 0; j < 8; j++)
                #pragma unroll
                for (int q = 0; q < 4; q++)
                    C2[j][q] += xch[(j * 4 + q) * 32 + lane];
            #pragma unroll
            for (int j = 0; j < 8; j++) {
                float2 bb = *(float2*)&sVb2[j * 8 + i * 2];
                C2[j][0] += bb.x; C2[j][1] += bb.y; C2[j][2] += bb.x; C2[j][3] += bb.y;
            }
            #pragma unroll
            for (int j = 0; j < 8; j++) {
                int c0 = j * 8 + i * 2;
                sEt[(c0    ) * 138 + r0    ] = __float2bfloat16(C2[j][0]);
                sEt[(c0 + 1) * 138 + r0    ] = __float2bfloat16(C2[j][1]);
                sEt[(c0    ) * 138 + r0 + 8] = __float2bfloat16(C2[j][2]);
                sEt[(c0 + 1) * 138 + r0 + 8] = __float2bfloat16(C2[j][3]);
            }
        }
    }
    __syncthreads();
    #pragma unroll
    for (int rep = 0; rep < 9; rep++) {
        int o = rep * 512 + tid;
        if (o < 2 * 32 * 65) sSpart[o] = 0.f;
    }
    __syncthreads();
    // ---- scatter MMA: 2-way k x 2-way m x 4-way n ----
    {
        int nq = w & 3, mh2 = (w >> 2) & 1, ksp = (w >> 3) & 1;
        float CS[2][4];
        #pragma unroll
        for (int j = 0; j < 2; j++) CS[j][0] = CS[j][1] = CS[j][2] = CS[j][3] = 0.f;
        #pragma unroll
        for (int ks2 = 0; ks2 < 4; ks2++) {
            int kb = ksp * 64 + ks2 * 16, k0 = kb + i * 2;
            int x0 = sWidx[k0], x1 = sWidx[k0 + 1], x2 = sWidx[k0 + 8], x3 = sWidx[k0 + 9];
            int mlo = mh2 * 16 + g, mhi = mlo + 8;
            uint32_t a0 = (x0 == mlo ? 0x3F80u : 0u) | (x1 == mlo ? 0x3F800000u : 0u);
            uint32_t a1 = (x0 == mhi ? 0x3F80u : 0u) | (x1 == mhi ? 0x3F800000u : 0u);
            uint32_t a2 = (x2 == mlo ? 0x3F80u : 0u) | (x3 == mlo ? 0x3F800000u : 0u);
            uint32_t a3 = (x2 == mhi ? 0x3F80u : 0u) | (x3 == mhi ? 0x3F800000u : 0u);
            #pragma unroll
            for (int j = 0; j < 2; j++) {
                int nrow = nq * 16 + j * 8 + g;
                mma16816(CS[j], a0, a1, a2, a3,
                         sEtu[nrow * 69 + (kb >> 1) + i], sEtu[nrow * 69 + (kb >> 1) + i + 4]);
            }
        }
        float* p = &sSpart[ksp * 2080];
        int m0 = mh2 * 16 + g;
        #pragma unroll
        for (int j = 0; j < 2; j++) {
            int c0 = nq * 16 + j * 8 + i * 2;
            p[m0 * 65 + c0]           = CS[j][0];
            p[m0 * 65 + c0 + 1]       = CS[j][1];
            p[(m0 + 8) * 65 + c0]     = CS[j][2];
            p[(m0 + 8) * 65 + c0 + 1] = CS[j][3];
        }
    }
    __syncthreads();
    int slice = bid & 7;
    #pragma unroll
    for (int rep = 0; rep < 4; rep++) {
        int o = rep * 512 + tid, m = o >> 6, c = o & 63;
        float v = sSpart[m * 65 + c] + sSpart[2080 + m * 65 + c];
        atomicAdd(&g_Sp[slice * 2048 + o], v);
    }
    if (tid < 32) atomicAdd(&g_cntp[slice * 32 + tid], (float)sCnt[tid]);
}

// ---------- finalize v2: 4 CTAs, d-column split; bit-identical loop orders ----------
__global__ void __launch_bounds__(512) finalize_kernel(
        const float* __restrict__ regvals, const float* __restrict__ wstrength,
        float* __restrict__ out, int Btot) {
    __shared__ float sS[2048], sATT[1024], sCnt[32], sM[32], sNR[512];
    int t = threadIdx.x;          // 512
    int db = blockIdx.x * 16;     // this block's d-column base (4 blocks x 16 cols)
    #pragma unroll
    for (int rep = 0; rep < 4; rep++) {
        int o = rep * 512 + t;
        float v = 0.f;
        #pragma unroll
        for (int sl = 0; sl < 8; sl++) v += g_Sp[sl * 2048 + o];
        sS[o] = v;
    }
    #pragma unroll
    for (int rep = 0; rep < 2; rep++) {
        int o = rep * 512 + t;
        sATT[o] = g_att[o];
    }
    if (t < 32) {
        float c = 0.f;
        #pragma unroll
        for (int sl = 0; sl < 8; sl++) c += g_cntp[sl * 32 + t];
        sCnt[t] = c;
    }
    __syncthreads();
    float invB = 1.f / (float)Btot;
    if (t < 32) {
        float m = 0.f;
        for (int i2 = 0; i2 < 32; i2++) m += sCnt[i2] * invB * sATT[i2 * 32 + t];
        sM[t] = m;
    }
    __syncthreads();
    float s = 1.f / (1.f + expf(-wstrength[0]));
    {
        int n = t >> 4, dl = t & 15, d = db + dl;   // 32 n x 16 d = 512
        int o = n * 64 + d;
        float as = 0.f;
        for (int i2 = 0; i2 < 32; i2++) as += sATT[i2 * 32 + n] * sS[i2 * 64 + d];
        float nr = (1.f - s * sM[n]) * regvals[o] + (s * invB) * as;
        out[(size_t)Btot * 64 + o] = nr;
        sNR[n * 16 + dl] = nr;
    }
    __syncthreads();
    {
        int i2 = t >> 4, dl = t & 15, d = db + dl;
        float r = 0.f;
        for (int n = 0; n < 32; n++) r += sATT[i2 * 32 + n] * sNR[n * 16 + dl];
        g_rout[i2 * 64 + d] = r;
    }
}

// ---------- read gather ----------
__global__ void __launch_bounds__(256) read_kernel(const int* __restrict__ ridx,
                                                   float* __restrict__ out) {
    __shared__ float4 sr[512];
    int t = threadIdx.x;
    #pragma unroll
    for (int rep = 0; rep < 2; rep++)
        sr[rep * 256 + t] = ((const float4*)g_rout)[rep * 256 + t];
    __syncthreads();
    int base = blockIdx.x * 128;
    #pragma unroll
    for (int it = 0; it < 8; it++) {
        int r = base + it * 16 + (t >> 4), cg = t & 15;
        int rv = ridx[r];
        float4 v = (rv == 31) ? make_float4(0.f, 0.f, 0.f, 0.f) : sr[rv * 16 + cg];
        ((float4*)out)[(size_t)r * 16 + cg] = v;
    }
}

// ---------- launcher ----------
extern "C" void kernel_launch(void* const* d_in, const int* in_sizes, int n_in,
                              void* d_out, int out_size) {
    const int*   wix  = (const int*)d_in[0];
    const float* wval = (const float*)d_in[1];
    const int*   rix  = (const int*)d_in[2];
    const float* regv = (const float*)d_in[3];
    const float* keys = (const float*)d_in[4];
    const float* qw1  = (const float*)d_in[5];
    const float* qb1  = (const float*)d_in[6];
    const float* qg1  = (const float*)d_in[7];
    const float* qbt1 = (const float*)d_in[8];
    const float* qw2  = (const float*)d_in[9];
    const float* qb2  = (const float*)d_in[10];
    const float* qg2  = (const float*)d_in[11];
    const float* qbt2 = (const float*)d_in[12];
    const float* qw3  = (const float*)d_in[13];
    const float* qb3  = (const float*)d_in[14];
    const float* vw1  = (const float*)d_in[15];
    const float* vb1  = (const float*)d_in[16];
    const float* vg1  = (const float*)d_in[17];
    const float* vbt1 = (const float*)d_in[18];
    const float* vw2  = (const float*)d_in[19];
    const float* vb2  = (const float*)d_in[20];
    const float* temp = (const float*)d_in[21];
    const float* wstr = (const float*)d_in[22];
    int B = in_sizes[0];

    cudaFuncSetAttribute(enc_kernel, cudaFuncAttributeMaxDynamicSharedMemorySize, ENC_SMEM_BYTES);

    setup_kernel<<<64, 1024>>>(qw1, qb1, qg1, qbt1, qw2, qb2, qg2, qbt2, qw3, qb3,
                               keys, temp, vw1, vw2);
    enc_kernel<<<B / 128, 512, ENC_SMEM_BYTES>>>(wval, wix, vb1, vg1, vbt1, vb2);
    finalize_kernel<<<4, 512>>>(regv, wstr, (float*)d_out, B);
    read_kernel<<<B / 128, 256>>>(rix, (float*)d_out);
}